// round 7
// baseline (speedup 1.0000x reference)
#include <cuda_runtime.h>
#include <cuda_fp16.h>

// ---------------------------------------------------------------------------
// MLMM electrostatics.
// E(p) = KE * q_v * ( q_u*chi - chi^3*(r.mu) + chi^5 * sum(O * Q') )
// with Q' = Q - (trQ/3) I (traceless), Q'22 = -(Q'00+Q'11).
//
// Gather record per ML atom: 32 bytes, 32B-aligned (ONE L2 sector):
//   float4 {q, mux, muy, muz} | 8 x fp16 {Q' components}
//
// R7: 2 pairs/thread, branch-free interleaved gather chains:
//  - thread t handles local pairs t and t+BLK (coalesced, conflict-free smem)
//  - masked/out-of-range lanes clamp idx to 0 and gather unconditionally
//    (all masked lanes share line 0 -> ~free), so both chains are pure
//    dataflow and ptxas interleaves them: 2x memory-level parallelism.
//  - gathers issued before the smem staging loop (latency hides behind it).
// ---------------------------------------------------------------------------

#define NML_MAX 50000
#define KE_CONST 14.399645351950548f
#define CUTOFF_A 10.0f
#define BLK 256
#define PPT 2
#define TILE (BLK * PPT)

// [2*u] : float4 {q, mu}; [2*u+1] : 8 fp16 Q' components
__device__ __align__(32) float4 g_packed[NML_MAX * 2];

__global__ void mlmm_prep_kernel(const float* __restrict__ q_ml,
                                 const float* __restrict__ mu,
                                 const float* __restrict__ Q,
                                 const float* __restrict__ e0,
                                 float* __restrict__ out,
                                 int nml) {
    int u = blockIdx.x * blockDim.x + threadIdx.x;
    if (u >= nml) return;

    out[u] = e0[u];

    float m0 = mu[3 * u + 0];
    float m1 = mu[3 * u + 1];
    float m2 = mu[3 * u + 2];

    float Qv[9];
#pragma unroll
    for (int k = 0; k < 9; k++) Qv[k] = Q[9 * u + k];
    float third_tr = (Qv[0] + Qv[4] + Qv[8]) * (1.0f / 3.0f);

    float t00 = Qv[0] - third_tr;
    float t11 = Qv[4] - third_tr;

    g_packed[2 * u + 0] = make_float4(q_ml[u], m0, m1, m2);

    __half2 h0 = __floats2half2_rn(t00,   Qv[1]);
    __half2 h1 = __floats2half2_rn(Qv[2], Qv[3]);
    __half2 h2 = __floats2half2_rn(t11,   Qv[5]);
    __half2 h3 = __floats2half2_rn(Qv[6], Qv[7]);

    uint4 packed;
    packed.x = *reinterpret_cast<unsigned int*>(&h0);
    packed.y = *reinterpret_cast<unsigned int*>(&h1);
    packed.z = *reinterpret_cast<unsigned int*>(&h2);
    packed.w = *reinterpret_cast<unsigned int*>(&h3);
    reinterpret_cast<uint4*>(g_packed)[2 * u + 1] = packed;
}

__global__ void __launch_bounds__(BLK)
mlmm_pair_kernel(const float* __restrict__ dist,
                 const float* __restrict__ vec,
                 const float* __restrict__ outer,
                 const int* __restrict__ idx_u,
                 const int* __restrict__ idx_v,
                 const float* __restrict__ q_mm,
                 float* __restrict__ out,
                 int n) {
    __shared__ float s_vec[TILE * 3];
    __shared__ float s_out[TILE * 9];

    long long base = (long long)blockIdx.x * TILE;
    int cnt = n - (int)base;
    if (cnt > TILE) cnt = TILE;

    // ---- phase 1: issue per-thread loads for BOTH pairs, branch-free ----
    int   l[PPT];
    bool  m[PPT];
    int   u[PPT], v[PPT];
    float d[PPT], qv[PPT];
    float4 p0[PPT];
    uint4  ph[PPT];

#pragma unroll
    for (int k = 0; k < PPT; k++) {
        l[k] = threadIdx.x + k * BLK;
        bool valid = (l[k] < cnt);
        long long i = base + l[k];
        d[k] = valid ? dist[i] : 1e30f;
        m[k] = (d[k] <= CUTOFF_A);
        u[k] = m[k] ? idx_u[i] : 0;   // clamp: masked lanes gather record 0
        v[k] = m[k] ? idx_v[i] : 0;
    }
#pragma unroll
    for (int k = 0; k < PPT; k++) {
        p0[k] = g_packed[2 * u[k] + 0];
        ph[k] = reinterpret_cast<const uint4*>(g_packed)[2 * u[k] + 1];
        qv[k] = __ldg(q_mm + v[k]);
    }

    // ---- phase 2: stage vec/outer tiles (coalesced float4) ----
    if (cnt == TILE) {
        const float4* v4 = (const float4*)(vec + 3 * base);
        float4*       sv = (float4*)s_vec;
#pragma unroll
        for (int t = threadIdx.x; t < TILE * 3 / 4; t += BLK) sv[t] = v4[t];

        const float4* o4 = (const float4*)(outer + 9 * base);
        float4*       so = (float4*)s_out;
#pragma unroll
        for (int t = threadIdx.x; t < TILE * 9 / 4; t += BLK) so[t] = o4[t];
    } else {
        for (int t = threadIdx.x; t < cnt * 3; t += BLK) s_vec[t] = vec[3 * base + t];
        for (int t = threadIdx.x; t < cnt * 9; t += BLK) s_out[t] = outer[9 * base + t];
    }
    __syncthreads();

    // ---- phase 3: math for both pairs, conditional scatter ----
#pragma unroll
    for (int k = 0; k < PPT; k++) {
        if (!m[k]) continue;

        const float* sv = s_vec + 3 * l[k];
        const float* so = s_out + 9 * l[k];
        float r0 = sv[0], r1 = sv[1], r2 = sv[2];
        float o00 = so[0], o01 = so[1], o02 = so[2];
        float o10 = so[3], o11 = so[4], o12 = so[5];
        float o20 = so[6], o21 = so[7], o22 = so[8];

        float chi  = __fdividef(1.0f, d[k]);
        float chi2 = chi * chi;
        float chi3 = chi2 * chi;
        float chi5 = chi3 * chi2;

        float e = p0[k].x * chi;                                    // charge
        e -= chi3 * (r0 * p0[k].y + r1 * p0[k].z + r2 * p0[k].w);   // dipole

        float2 c0 = __half22float2(*reinterpret_cast<__half2*>(&ph[k].x));
        float2 c1 = __half22float2(*reinterpret_cast<__half2*>(&ph[k].y));
        float2 c2 = __half22float2(*reinterpret_cast<__half2*>(&ph[k].z));
        float2 c3 = __half22float2(*reinterpret_cast<__half2*>(&ph[k].w));

        float dot9 = c0.x * (o00 - o22)
                   + c2.x * (o11 - o22)
                   + c0.y * o01 + c1.x * o02 + c1.y * o10
                   + c2.y * o12 + c3.x * o20 + c3.y * o21;
        e += chi5 * dot9;                                           // quadrupole

        e *= KE_CONST * qv[k];

        atomicAdd(out + u[k], e);
    }
}

extern "C" void kernel_launch(void* const* d_in, const int* in_sizes, int n_in,
                              void* d_out, int out_size) {
    const float* q_ml  = (const float*)d_in[0];  // [NML]
    const float* q_mm  = (const float*)d_in[1];  // [NMM]
    const float* mu    = (const float*)d_in[2];  // [NML,3]
    const float* Q     = (const float*)d_in[3];  // [NML,3,3]
    const float* e0    = (const float*)d_in[4];  // [NML]
    const float* dist  = (const float*)d_in[5];  // [P]
    const float* vec   = (const float*)d_in[6];  // [P,3]
    const float* outer = (const float*)d_in[7];  // [P,3,3]
    const int*   idx_u = (const int*)d_in[8];    // [P] int32
    const int*   idx_v = (const int*)d_in[9];    // [P] int32

    float* out = (float*)d_out;

    int nml = in_sizes[0];
    int P   = in_sizes[5];

    {
        int threads = 256;
        int blocks  = (nml + threads - 1) / threads;
        mlmm_prep_kernel<<<blocks, threads>>>(q_ml, mu, Q, e0, out, nml);
    }
    {
        int blocks = (P + TILE - 1) / TILE;
        mlmm_pair_kernel<<<blocks, BLK>>>(dist, vec, outer, idx_u, idx_v,
                                          q_mm, out, P);
    }
}